// round 1
// baseline (speedup 1.0000x reference)
#include <cuda_runtime.h>
#include <cstdint>

// ---------------- problem constants ----------------
#define TB 16
#define TN 1024
#define TD 768
#define TH 12
#define TP 16
#define THD 64
#define TFF 3072
#define TNK (TP + TN)      // 1040
#define TBH (TB * TH)      // 192
#define TM (TB * TN)       // 16384

// ---------------- scratch (device globals; no allocations allowed) ----------------
__device__ float g_h[(size_t)TM * TD];            // LN1 out, reused as LN2 out
__device__ float g_qkv[(size_t)TM * 3 * TD];
__device__ float g_qb[(size_t)TBH * TN * THD];    // reused as permuted attn out
__device__ float g_kb[(size_t)TBH * TNK * THD];
__device__ float g_vb[(size_t)TBH * TNK * THD];
__device__ float g_s[(size_t)TBH * TN * TNK];     // attention logits / probs (818 MB)
__device__ float g_ob[(size_t)TBH * TN * THD];
__device__ float g_x1[(size_t)TM * TD];
__device__ float g_mm[(size_t)TM * TFF];

// ---------------- helpers ----------------
__device__ __forceinline__ uint32_t f2tf(float f) {
    uint32_t u;
    asm("cvt.rna.tf32.f32 %0, %1;" : "=r"(u) : "f"(f));
    return u;
}

__device__ __forceinline__ void mma8(float c[4], const uint32_t a[4], const uint32_t b[2]) {
    asm volatile(
        "mma.sync.aligned.m16n8k8.row.col.f32.tf32.tf32.f32 "
        "{%0,%1,%2,%3},{%4,%5,%6,%7},{%8,%9},{%0,%1,%2,%3};\n"
        : "+f"(c[0]), "+f"(c[1]), "+f"(c[2]), "+f"(c[3])
        : "r"(a[0]), "r"(a[1]), "r"(a[2]), "r"(a[3]), "r"(b[0]), "r"(b[1]));
}

// ---------------- generic tiled TF32 GEMM ----------------
// C[z] = A[z] (MxK, lda=K) @ B[z] where:
//   BT=true : B is [N,K] (lda=K), C = A @ B^T
//   BT=false: B is [K,N] (lda=N), C = A @ B
// Epilogue: +bias[n], QuickGELU, +res[m*N+n], all optional. NG guards the N dim.
// Block tile 128x128, K-tile 16, 256 threads, warp tile 64x32 (2x4 warp grid).
template <bool BT, bool BIAS, bool RES, bool GELU, bool NG>
__global__ void __launch_bounds__(256)
gemm_kernel(const float* __restrict__ A, const float* __restrict__ B,
            const float* __restrict__ bias, const float* __restrict__ res,
            float* __restrict__ C, int M, int N, int K,
            long long zsA, long long zsB, long long zsC) {
    __shared__ float sA[2][128 * 20];   // pad 20: conflict-free frag LDS
    __shared__ float sB[2][128 * 20];

    const int z = blockIdx.z;
    A += (long long)z * zsA;
    B += (long long)z * zsB;
    C += (long long)z * zsC;

    const int m0 = blockIdx.y * 128;
    const int n0 = blockIdx.x * 128;
    const int t = threadIdx.x;
    const int warp = t >> 5, lane = t & 31;
    const int wm = (warp & 1) * 64, wn = (warp >> 1) * 32;
    const int g = lane >> 2, tg = lane & 3;

    float acc[4][4][4];
#pragma unroll
    for (int i = 0; i < 4; i++)
#pragma unroll
        for (int j = 0; j < 4; j++)
#pragma unroll
            for (int r = 0; r < 4; r++) acc[i][j][r] = 0.f;

    const int nk = K >> 4;

    // global->reg staging
    float4 ra[2], rb[2];
    const int arow = t >> 2, ac = (t & 3) * 4;      // 128x16 tile: 2 float4 per thread
    const int bk = t >> 5, bn4 = (t & 31) * 4;      // BN path: 16x128 tile

    auto gload = [&](int kt) {
        const int k0 = kt << 4;
#pragma unroll
        for (int u = 0; u < 2; u++)
            ra[u] = *(const float4*)(A + (long long)(m0 + arow + u * 64) * K + k0 + ac);
        if (BT) {
#pragma unroll
            for (int u = 0; u < 2; u++) {
                int rown = n0 + arow + u * 64;
                if (!NG || rown < N)
                    rb[u] = *(const float4*)(B + (long long)rown * K + k0 + ac);
                else
                    rb[u] = make_float4(0.f, 0.f, 0.f, 0.f);
            }
        } else {
#pragma unroll
            for (int u = 0; u < 2; u++) {
                if (!NG || n0 + bn4 < N)
                    rb[u] = *(const float4*)(B + (long long)(k0 + bk + u * 8) * N + n0 + bn4);
                else
                    rb[u] = make_float4(0.f, 0.f, 0.f, 0.f);
            }
        }
    };

    auto sstore = [&](int buf) {
#pragma unroll
        for (int u = 0; u < 2; u++) {
            float* p = &sA[buf][(arow + u * 64) * 20 + ac];
            p[0] = ra[u].x; p[1] = ra[u].y; p[2] = ra[u].z; p[3] = ra[u].w;
        }
        if (BT) {
#pragma unroll
            for (int u = 0; u < 2; u++) {
                float* p = &sB[buf][(arow + u * 64) * 20 + ac];
                p[0] = rb[u].x; p[1] = rb[u].y; p[2] = rb[u].z; p[3] = rb[u].w;
            }
        } else {
#pragma unroll
            for (int u = 0; u < 2; u++) {
                int k = bk + u * 8;
                sB[buf][(bn4 + 0) * 20 + k] = rb[u].x;
                sB[buf][(bn4 + 1) * 20 + k] = rb[u].y;
                sB[buf][(bn4 + 2) * 20 + k] = rb[u].z;
                sB[buf][(bn4 + 3) * 20 + k] = rb[u].w;
            }
        }
    };

    gload(0);
    sstore(0);
    __syncthreads();

    int buf = 0;
    for (int kt = 0; kt < nk; kt++) {
        if (kt + 1 < nk) gload(kt + 1);
#pragma unroll
        for (int ks = 0; ks < 16; ks += 8) {
            uint32_t af[4][4], bf[4][2];
#pragma unroll
            for (int i = 0; i < 4; i++) {
                const float* pa = &sA[buf][(wm + i * 16 + g) * 20 + ks + tg];
                af[i][0] = f2tf(pa[0]);
                af[i][1] = f2tf(pa[8 * 20]);
                af[i][2] = f2tf(pa[4]);
                af[i][3] = f2tf(pa[8 * 20 + 4]);
            }
#pragma unroll
            for (int j = 0; j < 4; j++) {
                const float* pb = &sB[buf][(wn + j * 8 + g) * 20 + ks + tg];
                bf[j][0] = f2tf(pb[0]);
                bf[j][1] = f2tf(pb[4]);
            }
#pragma unroll
            for (int i = 0; i < 4; i++)
#pragma unroll
                for (int j = 0; j < 4; j++) mma8(acc[i][j], af[i], bf[j]);
        }
        if (kt + 1 < nk) sstore(buf ^ 1);
        __syncthreads();
        buf ^= 1;
    }

    // epilogue
#pragma unroll
    for (int i = 0; i < 4; i++) {
#pragma unroll
        for (int j = 0; j < 4; j++) {
            int m = m0 + wm + i * 16 + g;
            int n = n0 + wn + j * 8 + tg * 2;
#pragma unroll
            for (int r = 0; r < 4; r++) {
                int mm = m + (r >> 1) * 8;
                int nn = n + (r & 1);
                if (NG && nn >= N) continue;
                float v = acc[i][j][r];
                if (BIAS) v += bias[nn];
                if (GELU) v = v / (1.f + __expf(-1.702f * v));
                if (RES) v += res[(long long)mm * N + nn];
                C[(long long)mm * N + nn] = v;
            }
        }
    }
}

// ---------------- LayerNorm (row=768, 256 threads/block) ----------------
__global__ void ln_kernel(const float* __restrict__ x, const float* __restrict__ gw,
                          const float* __restrict__ bw, float* __restrict__ out) {
    long long row = blockIdx.x;
    const float* xr = x + row * TD;
    float* orow = out + row * TD;
    int t = threadIdx.x;
    float v[3];
    float s = 0.f, s2 = 0.f;
#pragma unroll
    for (int i = 0; i < 3; i++) {
        v[i] = xr[t + i * 256];
        s += v[i];
        s2 += v[i] * v[i];
    }
#pragma unroll
    for (int o = 16; o > 0; o >>= 1) {
        s += __shfl_xor_sync(0xffffffffu, s, o);
        s2 += __shfl_xor_sync(0xffffffffu, s2, o);
    }
    __shared__ float r1[8], r2[8];
    if ((t & 31) == 0) { r1[t >> 5] = s; r2[t >> 5] = s2; }
    __syncthreads();
    s = 0.f; s2 = 0.f;
#pragma unroll
    for (int w = 0; w < 8; w++) { s += r1[w]; s2 += r2[w]; }
    float mu = s * (1.f / TD);
    float var = s2 * (1.f / TD) - mu * mu;
    float inv = rsqrtf(var + 1e-5f);
#pragma unroll
    for (int i = 0; i < 3; i++) {
        int c = t + i * 256;
        orow[c] = (v[i] - mu) * inv * gw[c] + bw[c];
    }
}

// ---------------- gathers / permutes ----------------
__global__ void gather_q_kernel(const float* __restrict__ qkv, float* __restrict__ dst) {
    int i = blockIdx.x * 256 + threadIdx.x;
    if (i >= TBH * TN * THD) return;
    int d = i & 63;
    int tmp = i >> 6;
    int n = tmp & (TN - 1);
    int zz = tmp >> 10;
    int b = zz / TH, h = zz % TH;
    dst[i] = qkv[(long long)(b * TN + n) * (3 * TD) + h * THD + d];
}

// sel=0: K (qkv col offset 768), sel=1: V (offset 1536); prompt[B,2,P,H,HD]
__global__ void gather_kv_kernel(const float* __restrict__ qkv, const float* __restrict__ prompt,
                                 float* __restrict__ dst, int sel) {
    int i = blockIdx.x * 256 + threadIdx.x;
    if (i >= TBH * TNK * THD) return;
    int d = i & 63;
    int tmp = i >> 6;
    int j = tmp % TNK;
    int zz = tmp / TNK;
    int b = zz / TH, h = zz % TH;
    float v;
    if (j < TP)
        v = prompt[(((long long)(b * 2 + sel) * TP + j) * TH + h) * THD + d];
    else
        v = qkv[(long long)(b * TN + (j - TP)) * (3 * TD) + (sel + 1) * TD + h * THD + d];
    dst[i] = v;
}

__global__ void operm_kernel(const float* __restrict__ ob, float* __restrict__ dst) {
    int i = blockIdx.x * 256 + threadIdx.x;
    if (i >= TM * TD) return;
    int c = i % TD;
    int m = i / TD;
    int h = c / THD, d = c % THD;
    int b = m >> 10, n = m & (TN - 1);
    dst[i] = ob[((long long)(b * TH + h) * TN + n) * THD + d];
}

// ---------------- row softmax over 1040 cols (scale applied here) ----------------
__global__ void softmax_kernel(float* __restrict__ s) {
    long long row = blockIdx.x;
    float* sr = s + row * TNK;
    int t = threadIdx.x;
    float v[5];
    float mx = -3.4e38f;
#pragma unroll
    for (int i = 0; i < 5; i++) {
        int c = t + i * 256;
        v[i] = (c < TNK) ? sr[c] * 0.125f : -3.4e38f;
        mx = fmaxf(mx, v[i]);
    }
#pragma unroll
    for (int o = 16; o > 0; o >>= 1) mx = fmaxf(mx, __shfl_xor_sync(0xffffffffu, mx, o));
    __shared__ float r1[8], r2[8];
    if ((t & 31) == 0) r1[t >> 5] = mx;
    __syncthreads();
    mx = r1[0];
#pragma unroll
    for (int w = 1; w < 8; w++) mx = fmaxf(mx, r1[w]);
    float sum = 0.f;
#pragma unroll
    for (int i = 0; i < 5; i++) {
        int c = t + i * 256;
        v[i] = (c < TNK) ? __expf(v[i] - mx) : 0.f;
        sum += v[i];
    }
#pragma unroll
    for (int o = 16; o > 0; o >>= 1) sum += __shfl_xor_sync(0xffffffffu, sum, o);
    if ((t & 31) == 0) r2[t >> 5] = sum;
    __syncthreads();
    sum = 0.f;
#pragma unroll
    for (int w = 0; w < 8; w++) sum += r2[w];
    float inv = 1.f / sum;
#pragma unroll
    for (int i = 0; i < 5; i++) {
        int c = t + i * 256;
        if (c < TNK) sr[c] = v[i] * inv;
    }
}

// ---------------- launch ----------------
extern "C" void kernel_launch(void* const* d_in, const int* in_sizes, int n_in,
                              void* d_out, int out_size) {
    const float* x      = (const float*)d_in[0];
    const float* prompt = (const float*)d_in[1];
    const float* qkv_w  = (const float*)d_in[2];
    const float* qkv_b  = (const float*)d_in[3];
    const float* out_w  = (const float*)d_in[4];
    const float* out_b  = (const float*)d_in[5];
    const float* ln1_g  = (const float*)d_in[6];
    const float* ln1_b  = (const float*)d_in[7];
    const float* ln2_g  = (const float*)d_in[8];
    const float* ln2_b  = (const float*)d_in[9];
    const float* fc1_w  = (const float*)d_in[10];
    const float* fc1_b  = (const float*)d_in[11];
    const float* fc2_w  = (const float*)d_in[12];
    const float* fc2_b  = (const float*)d_in[13];
    float* out = (float*)d_out;

    float *ph, *pqkv, *pqb, *pkb, *pvb, *ps, *pob, *px1, *pm;
    cudaGetSymbolAddress((void**)&ph, g_h);
    cudaGetSymbolAddress((void**)&pqkv, g_qkv);
    cudaGetSymbolAddress((void**)&pqb, g_qb);
    cudaGetSymbolAddress((void**)&pkb, g_kb);
    cudaGetSymbolAddress((void**)&pvb, g_vb);
    cudaGetSymbolAddress((void**)&ps, g_s);
    cudaGetSymbolAddress((void**)&pob, g_ob);
    cudaGetSymbolAddress((void**)&px1, g_x1);
    cudaGetSymbolAddress((void**)&pm, g_mm);

    // 1. LN1: x -> h
    ln_kernel<<<TM, 256>>>(x, ln1_g, ln1_b, ph);

    // 2. qkv = h @ qkv_w^T + qkv_b   [16384, 2304]
    gemm_kernel<true, true, false, false, false>
        <<<dim3(3 * TD / 128, TM / 128, 1), 256>>>(ph, qkv_w, qkv_b, nullptr, pqkv,
                                                   TM, 3 * TD, TD, 0, 0, 0);

    // 3. gather Q / K / V into head-contiguous buffers (prompt concat for K,V)
    gather_q_kernel<<<(TBH * TN * THD + 255) / 256, 256>>>(pqkv, pqb);
    gather_kv_kernel<<<(TBH * TNK * THD + 255) / 256, 256>>>(pqkv, prompt, pkb, 0);
    gather_kv_kernel<<<(TBH * TNK * THD + 255) / 256, 256>>>(pqkv, prompt, pvb, 1);

    // 4. S = Q @ K^T  (batched over 192 heads)  [1024, 1040]
    gemm_kernel<true, false, false, false, true>
        <<<dim3((TNK + 127) / 128, TN / 128, TBH), 256>>>(
            pqb, pkb, nullptr, nullptr, ps, TN, TNK, THD,
            (long long)TN * THD, (long long)TNK * THD, (long long)TN * TNK);

    // 5. softmax(S * 0.125) rowwise
    softmax_kernel<<<TBH * TN, 256>>>(ps);

    // 6. O = S @ V   (batched)  [1024, 64]
    gemm_kernel<false, false, false, false, true>
        <<<dim3(1, TN / 128, TBH), 256>>>(
            ps, pvb, nullptr, nullptr, pob, TN, THD, TNK,
            (long long)TN * TNK, (long long)TNK * THD, (long long)TN * THD);

    // 7. permute heads back -> [16384, 768]  (reuse g_qb as scratch)
    operm_kernel<<<(TM * TD + 255) / 256, 256>>>(pob, pqb);

    // 8. x1 = x + O @ out_w^T + out_b
    gemm_kernel<true, true, true, false, false>
        <<<dim3(TD / 128, TM / 128, 1), 256>>>(pqb, out_w, out_b, x, px1,
                                               TM, TD, TD, 0, 0, 0);

    // 9. LN2: x1 -> h (reuse)
    ln_kernel<<<TM, 256>>>(px1, ln2_g, ln2_b, ph);

    // 10. m = QuickGELU(h @ fc1_w^T + fc1_b)  [16384, 3072]
    gemm_kernel<true, true, false, true, false>
        <<<dim3(TFF / 128, TM / 128, 1), 256>>>(ph, fc1_w, fc1_b, nullptr, pm,
                                                TM, TFF, TD, 0, 0, 0);

    // 11. out = x1 + m @ fc2_w^T + fc2_b
    gemm_kernel<true, true, true, false, false>
        <<<dim3(TD / 128, TM / 128, 1), 256>>>(pm, fc2_w, fc2_b, px1, out,
                                               TM, TD, TFF, 0, 0, 0);
}

// round 2
// speedup vs baseline: 1.3862x; 1.3862x over previous
#include <cuda_runtime.h>
#include <cstdint>

// ---------------- problem constants ----------------
#define TB 16
#define TN 1024
#define TD 768
#define TH 12
#define TP 16
#define THD 64
#define TFF 3072
#define TNK (TP + TN)      // 1040
#define TBH (TB * TH)      // 192
#define TM (TB * TN)       // 16384

// ---------------- scratch (device globals; no allocations allowed) ----------------
__device__ float g_h[(size_t)TM * TD];            // LN1/LN2 out
__device__ float g_qkv[(size_t)TM * 3 * TD];
__device__ float g_kb[(size_t)TBH * TNK * THD];
__device__ float g_vb[(size_t)TBH * TNK * THD];
__device__ float g_ao[(size_t)TM * TD];           // attention out, [B,N,D]
__device__ float g_x1[(size_t)TM * TD];
__device__ float g_mm[(size_t)TM * TFF];

// ---------------- helpers ----------------
__device__ __forceinline__ uint32_t f2tf(float f) {
    uint32_t u;
    asm("cvt.rna.tf32.f32 %0, %1;" : "=r"(u) : "f"(f));
    return u;
}
__device__ __forceinline__ float f2tff(float f) {   // tf32 bits viewed as float
    return __uint_as_float(f2tf(f));
}

__device__ __forceinline__ void mma8(float c[4], const uint32_t a[4], const uint32_t b[2]) {
    asm volatile(
        "mma.sync.aligned.m16n8k8.row.col.f32.tf32.tf32.f32 "
        "{%0,%1,%2,%3},{%4,%5,%6,%7},{%8,%9},{%0,%1,%2,%3};\n"
        : "+f"(c[0]), "+f"(c[1]), "+f"(c[2]), "+f"(c[3])
        : "r"(a[0]), "r"(a[1]), "r"(a[2]), "r"(a[3]), "r"(b[0]), "r"(b[1]));
}

// ---------------- generic tiled TF32 GEMM (TF32 pre-converted at smem store) ----
// C = A (MxK) @ B^T (B is [N,K]).  Epilogue: +bias[n], QuickGELU, +res, optional.
// Block tile 128x128, K-tile 16, 256 threads, warp tile 64x32 (2x4 warp grid).
template <bool BIAS, bool RES, bool GELU>
__global__ void __launch_bounds__(256)
gemm_kernel(const float* __restrict__ A, const float* __restrict__ B,
            const float* __restrict__ bias, const float* __restrict__ res,
            float* __restrict__ C, int M, int N, int K) {
    __shared__ float sA[2][128 * 20];
    __shared__ float sB[2][128 * 20];

    const int m0 = blockIdx.y * 128;
    const int n0 = blockIdx.x * 128;
    const int t = threadIdx.x;
    const int warp = t >> 5, lane = t & 31;
    const int wm = (warp & 1) * 64, wn = (warp >> 1) * 32;
    const int g = lane >> 2, tg = lane & 3;

    float acc[4][4][4];
#pragma unroll
    for (int i = 0; i < 4; i++)
#pragma unroll
        for (int j = 0; j < 4; j++)
#pragma unroll
            for (int r = 0; r < 4; r++) acc[i][j][r] = 0.f;

    const int nk = K >> 4;
    float4 ra[2], rb[2];
    const int arow = t >> 2, ac = (t & 3) * 4;

    auto gload = [&](int kt) {
        const int k0 = kt << 4;
#pragma unroll
        for (int u = 0; u < 2; u++)
            ra[u] = *(const float4*)(A + (long long)(m0 + arow + u * 64) * K + k0 + ac);
#pragma unroll
        for (int u = 0; u < 2; u++)
            rb[u] = *(const float4*)(B + (long long)(n0 + arow + u * 64) * K + k0 + ac);
    };

    auto sstore = [&](int buf) {
#pragma unroll
        for (int u = 0; u < 2; u++) {
            float* p = &sA[buf][(arow + u * 64) * 20 + ac];
            p[0] = f2tff(ra[u].x); p[1] = f2tff(ra[u].y);
            p[2] = f2tff(ra[u].z); p[3] = f2tff(ra[u].w);
        }
#pragma unroll
        for (int u = 0; u < 2; u++) {
            float* p = &sB[buf][(arow + u * 64) * 20 + ac];
            p[0] = f2tff(rb[u].x); p[1] = f2tff(rb[u].y);
            p[2] = f2tff(rb[u].z); p[3] = f2tff(rb[u].w);
        }
    };

    gload(0);
    sstore(0);
    __syncthreads();

    int buf = 0;
    for (int kt = 0; kt < nk; kt++) {
        if (kt + 1 < nk) gload(kt + 1);
#pragma unroll
        for (int ks = 0; ks < 16; ks += 8) {
            uint32_t af[4][4], bf[4][2];
#pragma unroll
            for (int i = 0; i < 4; i++) {
                const float* pa = &sA[buf][(wm + i * 16 + g) * 20 + ks + tg];
                af[i][0] = __float_as_uint(pa[0]);
                af[i][1] = __float_as_uint(pa[8 * 20]);
                af[i][2] = __float_as_uint(pa[4]);
                af[i][3] = __float_as_uint(pa[8 * 20 + 4]);
            }
#pragma unroll
            for (int j = 0; j < 4; j++) {
                const float* pb = &sB[buf][(wn + j * 8 + g) * 20 + ks + tg];
                bf[j][0] = __float_as_uint(pb[0]);
                bf[j][1] = __float_as_uint(pb[4]);
            }
#pragma unroll
            for (int i = 0; i < 4; i++)
#pragma unroll
                for (int j = 0; j < 4; j++) mma8(acc[i][j], af[i], bf[j]);
        }
        if (kt + 1 < nk) sstore(buf ^ 1);
        __syncthreads();
        buf ^= 1;
    }

#pragma unroll
    for (int i = 0; i < 4; i++) {
#pragma unroll
        for (int j = 0; j < 4; j++) {
            int m = m0 + wm + i * 16 + g;
            int n = n0 + wn + j * 8 + tg * 2;
#pragma unroll
            for (int r = 0; r < 4; r++) {
                int mm = m + (r >> 1) * 8;
                int nn = n + (r & 1);
                float v = acc[i][j][r];
                if (BIAS) v += bias[nn];
                if (GELU) v = v / (1.f + __expf(-1.702f * v));
                if (RES) v += res[(long long)mm * N + nn];
                C[(long long)mm * N + nn] = v;
            }
        }
    }
}

// ---------------- LayerNorm ----------------
__global__ void ln_kernel(const float* __restrict__ x, const float* __restrict__ gw,
                          const float* __restrict__ bw, float* __restrict__ out) {
    long long row = blockIdx.x;
    const float* xr = x + row * TD;
    float* orow = out + row * TD;
    int t = threadIdx.x;
    float v[3];
    float s = 0.f, s2 = 0.f;
#pragma unroll
    for (int i = 0; i < 3; i++) {
        v[i] = xr[t + i * 256];
        s += v[i];
        s2 += v[i] * v[i];
    }
#pragma unroll
    for (int o = 16; o > 0; o >>= 1) {
        s += __shfl_xor_sync(0xffffffffu, s, o);
        s2 += __shfl_xor_sync(0xffffffffu, s2, o);
    }
    __shared__ float r1[8], r2[8];
    if ((t & 31) == 0) { r1[t >> 5] = s; r2[t >> 5] = s2; }
    __syncthreads();
    s = 0.f; s2 = 0.f;
#pragma unroll
    for (int w = 0; w < 8; w++) { s += r1[w]; s2 += r2[w]; }
    float mu = s * (1.f / TD);
    float var = s2 * (1.f / TD) - mu * mu;
    float inv = rsqrtf(var + 1e-5f);
#pragma unroll
    for (int i = 0; i < 3; i++) {
        int c = t + i * 256;
        orow[c] = (v[i] - mu) * inv * gw[c] + bw[c];
    }
}

// ---------------- K/V gather (prompt concat) ----------------
// sel=0: K (qkv col offset 768), sel=1: V (offset 1536); prompt[B,2,P,H,HD]
__global__ void gather_kv_kernel(const float* __restrict__ qkv, const float* __restrict__ prompt,
                                 float* __restrict__ dst, int sel) {
    int i = blockIdx.x * 256 + threadIdx.x;
    if (i >= TBH * TNK * THD) return;
    int d = i & 63;
    int tmp = i >> 6;
    int j = tmp % TNK;
    int zz = tmp / TNK;
    int b = zz / TH, h = zz % TH;
    float v;
    if (j < TP)
        v = prompt[(((long long)(b * 2 + sel) * TP + j) * TH + h) * THD + d];
    else
        v = qkv[(long long)(b * TN + (j - TP)) * (3 * TD) + (sel + 1) * TD + h * THD + d];
    dst[i] = v;
}

// ---------------- fused flash attention ----------------
// grid (TN/128, TBH), 256 threads (8 warps, 16 q-rows each).
// Q read straight from g_qkv; K/V from gathered buffers; O written in [B,N,D].
#define FA_SMEM_BYTES ((2 * 64 * 68 + 128 * 68) * 4)

__global__ void __launch_bounds__(256)
flash_kernel(const float* __restrict__ qkv, const float* __restrict__ Kb,
             const float* __restrict__ Vb, float* __restrict__ O) {
    extern __shared__ float sm[];
    float* sK = sm;                 // [64][68]
    float* sV = sm + 64 * 68;       // [64][68]
    float* sP = sm + 2 * 64 * 68;   // [128][68], also Q staging

    const int z = blockIdx.y;
    const int b = z / TH, h = z % TH;
    const int q0 = blockIdx.x * 128;
    const int t = threadIdx.x, warp = t >> 5, lane = t & 31;
    const int g = lane >> 2, tg = lane & 3;
    const int wm = warp * 16;

    // stage Q tile [128,64] into sP, then preload register tf32 frags
#pragma unroll
    for (int u = 0; u < 8; u++) {
        int idx = t + u * 256;
        int r = idx >> 4, c4 = (idx & 15) * 4;
        float4 v = *(const float4*)(qkv + (long long)(b * TN + q0 + r) * (3 * TD) + h * THD + c4);
        float* p = &sP[r * 68 + c4];
        p[0] = v.x; p[1] = v.y; p[2] = v.z; p[3] = v.w;
    }
    __syncthreads();
    uint32_t qf[8][4];
#pragma unroll
    for (int ks = 0; ks < 8; ks++) {
        const float* pa = &sP[(wm + g) * 68 + ks * 8 + tg];
        qf[ks][0] = f2tf(pa[0]);
        qf[ks][1] = f2tf(pa[8 * 68]);
        qf[ks][2] = f2tf(pa[4]);
        qf[ks][3] = f2tf(pa[8 * 68 + 4]);
    }
    __syncthreads();

    float acc[8][4];
#pragma unroll
    for (int j = 0; j < 8; j++)
#pragma unroll
        for (int r = 0; r < 4; r++) acc[j][r] = 0.f;
    float m0 = -1e30f, m1 = -1e30f, l0 = 0.f, l1 = 0.f;

    const float* Kz = Kb + (long long)z * TNK * THD;
    const float* Vz = Vb + (long long)z * TNK * THD;

    for (int t0 = 0; t0 < TNK; t0 += 64) {   // 17 tiles
        // load K/V tile [64,64]
#pragma unroll
        for (int u = 0; u < 4; u++) {
            int idx = t + u * 256;
            int r = idx >> 4, c4 = (idx & 15) * 4;
            int key = t0 + r;
            float4 kk, vv;
            if (key < TNK) {
                kk = *(const float4*)(Kz + (long long)key * THD + c4);
                vv = *(const float4*)(Vz + (long long)key * THD + c4);
            } else {
                kk = make_float4(0.f, 0.f, 0.f, 0.f);
                vv = kk;
            }
            float* pk = &sK[r * 68 + c4];
            pk[0] = kk.x; pk[1] = kk.y; pk[2] = kk.z; pk[3] = kk.w;
            float* pv = &sV[r * 68 + c4];
            pv[0] = vv.x; pv[1] = vv.y; pv[2] = vv.z; pv[3] = vv.w;
        }
        __syncthreads();

        // S = Q @ K^T  (16 x 64 per warp)
        float s[8][4];
#pragma unroll
        for (int j = 0; j < 8; j++) {
            s[j][0] = s[j][1] = s[j][2] = s[j][3] = 0.f;
#pragma unroll
            for (int ks = 0; ks < 8; ks++) {
                uint32_t bf[2];
                const float* pb = &sK[(j * 8 + g) * 68 + ks * 8 + tg];
                bf[0] = f2tf(pb[0]);
                bf[1] = f2tf(pb[4]);
                mma8(s[j], qf[ks], bf);
            }
        }

        // online softmax
        float mx0 = -1e30f, mx1 = -1e30f;
#pragma unroll
        for (int j = 0; j < 8; j++) {
            int k0 = t0 + j * 8 + 2 * tg;
            if (k0 >= TNK) { s[j][0] = -1e30f; s[j][2] = -1e30f; }
            else           { s[j][0] *= 0.125f; s[j][2] *= 0.125f; }
            if (k0 + 1 >= TNK) { s[j][1] = -1e30f; s[j][3] = -1e30f; }
            else               { s[j][1] *= 0.125f; s[j][3] *= 0.125f; }
            mx0 = fmaxf(mx0, fmaxf(s[j][0], s[j][1]));
            mx1 = fmaxf(mx1, fmaxf(s[j][2], s[j][3]));
        }
        mx0 = fmaxf(mx0, __shfl_xor_sync(0xffffffffu, mx0, 1));
        mx0 = fmaxf(mx0, __shfl_xor_sync(0xffffffffu, mx0, 2));
        mx1 = fmaxf(mx1, __shfl_xor_sync(0xffffffffu, mx1, 1));
        mx1 = fmaxf(mx1, __shfl_xor_sync(0xffffffffu, mx1, 2));
        float mn0 = fmaxf(m0, mx0), mn1 = fmaxf(m1, mx1);
        float a0 = __expf(m0 - mn0), a1 = __expf(m1 - mn1);
        m0 = mn0; m1 = mn1;
        float sum0 = 0.f, sum1 = 0.f;
#pragma unroll
        for (int j = 0; j < 8; j++) {
            s[j][0] = __expf(s[j][0] - mn0);
            s[j][1] = __expf(s[j][1] - mn0);
            s[j][2] = __expf(s[j][2] - mn1);
            s[j][3] = __expf(s[j][3] - mn1);
            sum0 += s[j][0] + s[j][1];
            sum1 += s[j][2] + s[j][3];
            float* pp = &sP[(wm + g) * 68 + j * 8 + 2 * tg];
            pp[0] = s[j][0]; pp[1] = s[j][1];
            pp[8 * 68] = s[j][2]; pp[8 * 68 + 1] = s[j][3];
        }
        sum0 += __shfl_xor_sync(0xffffffffu, sum0, 1);
        sum0 += __shfl_xor_sync(0xffffffffu, sum0, 2);
        sum1 += __shfl_xor_sync(0xffffffffu, sum1, 1);
        sum1 += __shfl_xor_sync(0xffffffffu, sum1, 2);
        l0 = l0 * a0 + sum0;
        l1 = l1 * a1 + sum1;
#pragma unroll
        for (int j = 0; j < 8; j++) {
            acc[j][0] *= a0; acc[j][1] *= a0;
            acc[j][2] *= a1; acc[j][3] *= a1;
        }
        __syncwarp();

        // O += P @ V
#pragma unroll
        for (int ks = 0; ks < 8; ks++) {
            uint32_t af[4];
            const float* pa = &sP[(wm + g) * 68 + ks * 8 + tg];
            af[0] = f2tf(pa[0]);
            af[1] = f2tf(pa[8 * 68]);
            af[2] = f2tf(pa[4]);
            af[3] = f2tf(pa[8 * 68 + 4]);
#pragma unroll
            for (int j = 0; j < 8; j++) {
                uint32_t bf[2];
                bf[0] = f2tf(sV[(ks * 8 + tg) * 68 + j * 8 + g]);
                bf[1] = f2tf(sV[(ks * 8 + tg + 4) * 68 + j * 8 + g]);
                mma8(acc[j], af, bf);
            }
        }
        __syncthreads();
    }

    // epilogue: normalize, write [B,N,D]
    float i0 = 1.f / l0, i1 = 1.f / l1;
    int q = q0 + wm + g;
#pragma unroll
    for (int j = 0; j < 8; j++) {
        long long base = ((long long)(b * TN + q)) * TD + h * THD + j * 8 + 2 * tg;
        O[base] = acc[j][0] * i0;
        O[base + 1] = acc[j][1] * i0;
        O[base + (long long)8 * TD] = acc[j][2] * i1;
        O[base + (long long)8 * TD + 1] = acc[j][3] * i1;
    }
}

// ---------------- launch ----------------
extern "C" void kernel_launch(void* const* d_in, const int* in_sizes, int n_in,
                              void* d_out, int out_size) {
    const float* x      = (const float*)d_in[0];
    const float* prompt = (const float*)d_in[1];
    const float* qkv_w  = (const float*)d_in[2];
    const float* qkv_b  = (const float*)d_in[3];
    const float* out_w  = (const float*)d_in[4];
    const float* out_b  = (const float*)d_in[5];
    const float* ln1_g  = (const float*)d_in[6];
    const float* ln1_b  = (const float*)d_in[7];
    const float* ln2_g  = (const float*)d_in[8];
    const float* ln2_b  = (const float*)d_in[9];
    const float* fc1_w  = (const float*)d_in[10];
    const float* fc1_b  = (const float*)d_in[11];
    const float* fc2_w  = (const float*)d_in[12];
    const float* fc2_b  = (const float*)d_in[13];
    float* out = (float*)d_out;

    float *ph, *pqkv, *pkb, *pvb, *pao, *px1, *pm;
    cudaGetSymbolAddress((void**)&ph, g_h);
    cudaGetSymbolAddress((void**)&pqkv, g_qkv);
    cudaGetSymbolAddress((void**)&pkb, g_kb);
    cudaGetSymbolAddress((void**)&pvb, g_vb);
    cudaGetSymbolAddress((void**)&pao, g_ao);
    cudaGetSymbolAddress((void**)&px1, g_x1);
    cudaGetSymbolAddress((void**)&pm, g_mm);

    cudaFuncSetAttribute(flash_kernel, cudaFuncAttributeMaxDynamicSharedMemorySize,
                         FA_SMEM_BYTES);

    // 1. LN1
    ln_kernel<<<TM, 256>>>(x, ln1_g, ln1_b, ph);

    // 2. qkv = h @ qkv_w^T + qkv_b
    gemm_kernel<true, false, false>
        <<<dim3(3 * TD / 128, TM / 128), 256>>>(ph, qkv_w, qkv_b, nullptr, pqkv,
                                                TM, 3 * TD, TD);

    // 3. gather K/V (prompt concat)
    gather_kv_kernel<<<(TBH * TNK * THD + 255) / 256, 256>>>(pqkv, prompt, pkb, 0);
    gather_kv_kernel<<<(TBH * TNK * THD + 255) / 256, 256>>>(pqkv, prompt, pvb, 1);

    // 4. fused flash attention -> [B,N,D]
    flash_kernel<<<dim3(TN / 128, TBH), 256, FA_SMEM_BYTES>>>(pqkv, pkb, pvb, pao);

    // 5. x1 = x + O @ out_w^T + out_b
    gemm_kernel<true, true, false>
        <<<dim3(TD / 128, TM / 128), 256>>>(pao, out_w, out_b, x, px1, TM, TD, TD);

    // 6. LN2
    ln_kernel<<<TM, 256>>>(px1, ln2_g, ln2_b, ph);

    // 7. m = QuickGELU(h @ fc1_w^T + fc1_b)
    gemm_kernel<true, false, true>
        <<<dim3(TFF / 128, TM / 128), 256>>>(ph, fc1_w, fc1_b, nullptr, pm, TM, TFF, TD);

    // 8. out = x1 + m @ fc2_w^T + fc2_b
    gemm_kernel<true, true, false>
        <<<dim3(TD / 128, TM / 128), 256>>>(pm, fc2_w, fc2_b, px1, out, TM, TD, TFF);
}